// round 17
// baseline (speedup 1.0000x reference)
#include <cuda_runtime.h>
#include <cstdint>

#define N_NODES 100000
#define IN_CH   512
#define HID     16
#define OUT_CH  64
#define MAX_E   3200000
#define NBLK    ((N_NODES + 255) / 256)   // 391 gemm tiles / scan blocks

typedef unsigned long long u64;

// ---------------- device scratch (static, no allocation) ----------------
// invariant: g_cnt all-zero at kernel_launch entry (zero-init first run;
// scan phase re-zeroes each run). g_c_scan reset by gather2.
__device__ float g_dinv[N_NODES];
__device__ int   g_cnt[N_NODES];
__device__ u64   g_bstate[NBLK];          // decoupled-lookback state (zeroed by k_hist)
__device__ int   g_rowptr[N_NODES + 1];
__device__ int   g_cur[N_NODES];
__device__ int   g_csr[MAX_E];            // src only, bucketed by dst
__device__ float g_h1[N_NODES * HID];     // h1' = (x@W1) * dinv   (pre-scaled)
__device__ float g_hr[N_NODES * HID];     // hr' = relu(conv1) * dinv (pre-scaled)
__device__ int   g_c_scan;                // completed scan blocks (release counter)

// ---------------- helpers ----------------
__device__ __forceinline__ u64 pack2(float lo, float hi) {
    u64 r; asm("mov.b64 %0, {%1, %2};" : "=l"(r) : "f"(lo), "f"(hi)); return r;
}
__device__ __forceinline__ u64 fma2(u64 a, u64 b, u64 c) {
    u64 d; asm("fma.rn.f32x2 %0, %1, %2, %3;" : "=l"(d) : "l"(a), "l"(b), "l"(c)); return d;
}
__device__ __forceinline__ float2 unpack2(u64 v) {
    float2 f; asm("mov.b64 {%0, %1}, %2;" : "=f"(f.x), "=f"(f.y) : "l"(v)); return f;
}
__device__ __forceinline__ void cpasync16(uint32_t saddr, const void* g, int srcbytes) {
    asm volatile("cp.async.cg.shared.global [%0], [%1], 16, %2;"
                 :: "r"(saddr), "l"(g), "r"(srcbytes));
}
__device__ __forceinline__ void cp_commit() {
    asm volatile("cp.async.commit_group;");
}
template <int N>
__device__ __forceinline__ void cp_wait() {
    asm volatile("cp.async.wait_group %0;" :: "n"(N));
}
__device__ __forceinline__ void spin_scan_done() {
    volatile int* p = &g_c_scan;
    while (*p < NBLK) __nanosleep(128);
}

// ---------------- GEMM1 tile: h1' = (x @ W1) * dinv (spin before epilogue) ----------------
#define XS_PITCH 20
#define NCHUNK   (IN_CH / 16)   // 32
__device__ __forceinline__ void gemm1_tile(const float* __restrict__ x,
                                           const float* __restrict__ W,
                                           int n, int tile) {
    __shared__ __align__(16) float xs[2][256 * XS_PITCH];  // 40 KB
    __shared__ __align__(16) u64   wp[2][8 * HID];         // 2 KB

    const int t = threadIdx.x;
    const int rowBase = tile * 256;
    const int rg = t >> 2;
    const int jg = t & 3;
    const int ko = (t & 3) * 4;

    auto stage_x = [&](int kk, int b) {
#pragma unroll
        for (int p = 0; p < 4; p++) {
            int row = (t >> 2) + p * 64;
            int grow = rowBase + row;
            bool ok = (grow < n);
            const float* gp = ok ? &x[(size_t)grow * IN_CH + kk + ko] : x;
            uint32_t sa = (uint32_t)__cvta_generic_to_shared(&xs[b][row * XS_PITCH + ko]);
            cpasync16(sa, gp, ok ? 16 : 0);
        }
    };
    auto stage_w = [&](int kk, int b) {
        if (t < 128) {
            int kp = t >> 4, j = t & 15;
            wp[b][kp * HID + j] = pack2(W[(kk + 2 * kp) * HID + j],
                                        W[(kk + 2 * kp + 1) * HID + j]);
        }
    };

    u64 acc[4][4];
#pragma unroll
    for (int r = 0; r < 4; r++)
#pragma unroll
        for (int j = 0; j < 4; j++) acc[r][j] = 0ull;

    stage_x(0, 0);
    stage_w(0, 0);
    cp_commit();

    int buf = 0;
    for (int c = 0; c < NCHUNK; c++) {
        if (c < NCHUNK - 1) {
            stage_x((c + 1) * 16, buf ^ 1);
            stage_w((c + 1) * 16, buf ^ 1);
            cp_commit();
            cp_wait<1>();
        } else {
            cp_wait<0>();
        }
        __syncthreads();

#pragma unroll
        for (int k4 = 0; k4 < 4; k4++) {
            u64 w0[4], w1[4];
            *reinterpret_cast<ulonglong2*>(&w0[0]) =
                *reinterpret_cast<const ulonglong2*>(&wp[buf][(2 * k4) * HID + jg * 4]);
            *reinterpret_cast<ulonglong2*>(&w0[2]) =
                *reinterpret_cast<const ulonglong2*>(&wp[buf][(2 * k4) * HID + jg * 4 + 2]);
            *reinterpret_cast<ulonglong2*>(&w1[0]) =
                *reinterpret_cast<const ulonglong2*>(&wp[buf][(2 * k4 + 1) * HID + jg * 4]);
            *reinterpret_cast<ulonglong2*>(&w1[2]) =
                *reinterpret_cast<const ulonglong2*>(&wp[buf][(2 * k4 + 1) * HID + jg * 4 + 2]);
#pragma unroll
            for (int r = 0; r < 4; r++) {
                ulonglong2 xq = *reinterpret_cast<const ulonglong2*>(
                    &xs[buf][(rg + 64 * r) * XS_PITCH + k4 * 4]);
#pragma unroll
                for (int j = 0; j < 4; j++) {
                    acc[r][j] = fma2(xq.x, w0[j], acc[r][j]);
                    acc[r][j] = fma2(xq.y, w1[j], acc[r][j]);
                }
            }
        }
        __syncthreads();
        buf ^= 1;
    }

    if (t == 0) spin_scan_done();
    __syncthreads();

#pragma unroll
    for (int r = 0; r < 4; r++) {
        int grow = rowBase + rg + 64 * r;
        if (grow < n) {
            float di = g_dinv[grow];
            float2 a0 = unpack2(acc[r][0]);
            float2 a1 = unpack2(acc[r][1]);
            float2 a2 = unpack2(acc[r][2]);
            float2 a3 = unpack2(acc[r][3]);
            reinterpret_cast<float4*>(&g_h1[(size_t)grow * HID])[jg] =
                make_float4((a0.x + a0.y) * di, (a1.x + a1.y) * di,
                            (a2.x + a2.y) * di, (a3.x + a3.y) * di);
        }
    }
}

// ---------------- scan block body (decoupled lookback; zeroes g_cnt behind itself) ----------------
__device__ __forceinline__ void scan_block(int sb, int n) {
    __shared__ int s[256];
    __shared__ int s_prefix;
    const int t = threadIdx.x;
    const int i = sb * 256 + t;
    int v = (i < n) ? g_cnt[i] : 0;
    if (i < n) g_cnt[i] = 0;
    s[t] = v;
    __syncthreads();
#pragma unroll
    for (int off = 1; off < 256; off <<= 1) {
        int add = (t >= off) ? s[t - off] : 0;
        __syncthreads();
        s[t] += add;
        __syncthreads();
    }
    int incl = s[t];
    int agg  = s[255];

    if (t == 0) {
        u64 pk = (sb == 0) ? ((2ull << 40) | (unsigned)agg)
                           : ((1ull << 40) | (unsigned)agg);
        atomicExch(&g_bstate[sb], pk);
        if (sb == 0) s_prefix = 0;
    }
    if (sb > 0 && t < 32) {
        int ex = 0;
        int base = sb;
        while (true) {
            int p = base - 32 + t;
            u64 st = (p >= 0) ? atomicAdd(&g_bstate[p], 0ull) : (2ull << 40);
            int flag = (int)(st >> 40);
            int val  = (int)(st & 0xFFFFFFFFu);
            if (!__all_sync(0xffffffffu, flag != 0)) continue;
            unsigned pm = __ballot_sync(0xffffffffu, flag == 2);
            int hi = pm ? (31 - __clz(pm)) : 0;
            int contrib = (pm == 0 || t >= hi) ? val : 0;
#pragma unroll
            for (int o = 16; o; o >>= 1)
                contrib += __shfl_xor_sync(0xffffffffu, contrib, o);
            ex += contrib;
            if (pm) break;
            base -= 32;
        }
        if (t == 0) {
            s_prefix = ex;
            atomicExch(&g_bstate[sb], (2ull << 40) | (unsigned)(ex + agg));
        }
    }
    __syncthreads();
    if (i < n) {
        int rp = s_prefix + incl - v;
        g_rowptr[i] = rp;
        g_cur[i] = rp;
        g_dinv[i] = rsqrtf((float)v + 1.0f);
        if (i == n - 1) g_rowptr[n] = rp + v;
    }
    __threadfence();
    __syncthreads();
    if (t == 0) atomicAdd(&g_c_scan, 1);
}

// ---------------- combined kernel: [gemm 391][scan 391][scatter] ----------------
__global__ void __launch_bounds__(256) k_ck(const float* __restrict__ x,
                                            const float* __restrict__ W,
                                            const int* __restrict__ src,
                                            const int* __restrict__ dst,
                                            int n, int e) {
    int b = blockIdx.x;
    if (b < NBLK) {
        gemm1_tile(x, W, n, b);
    } else if (b < 2 * NBLK) {
        scan_block(b - NBLK, n);
    } else {
        if (threadIdx.x == 0) spin_scan_done();
        __syncthreads();
        int i = (b - 2 * NBLK) * 256 + threadIdx.x;
        if (i < e) {
            int d = dst[i];
            int pos = atomicAdd(&g_cur[d], 1);
            g_csr[pos] = src[i];
        }
    }
}

// ---------------- hist (also zeroes lookback state for this run) ----------------
__global__ void k_hist(const int* __restrict__ dst, int e) {
    int b = blockIdx.x, t = threadIdx.x;
    if (b < 2) {
        int z = b * 256 + t;
        if (z < NBLK) g_bstate[z] = 0ull;
    }
    int i = b * 256 + t;
    if (i < e) atomicAdd(&g_cnt[dst[i]], 1);
}

// ---------------- gather layer 1: eighth-warp/edge, float4 lanes ----------------
__global__ void __launch_bounds__(256) k_gather1(const float* __restrict__ b1, int n) {
    int wid = (blockIdx.x * 256 + threadIdx.x) >> 5;
    if (wid >= n) return;
    int lane = threadIdx.x & 31;
    int c  = lane & 3;    // column quad (4 floats)
    int eo = lane >> 2;   // edge slot 0..7
    int row = g_rowptr[wid], end = g_rowptr[wid + 1];

    float4 acc = make_float4(0.f, 0.f, 0.f, 0.f);
    for (int i = row + eo; i < end; i += 8) {
        int s = g_csr[i];
        float4 hv = *reinterpret_cast<const float4*>(&g_h1[(size_t)s * HID + c * 4]);
        acc.x += hv.x; acc.y += hv.y; acc.z += hv.z; acc.w += hv.w;
    }
#pragma unroll
    for (int o = 4; o <= 16; o <<= 1) {
        acc.x += __shfl_xor_sync(0xffffffffu, acc.x, o);
        acc.y += __shfl_xor_sync(0xffffffffu, acc.y, o);
        acc.z += __shfl_xor_sync(0xffffffffu, acc.z, o);
        acc.w += __shfl_xor_sync(0xffffffffu, acc.w, o);
    }

    if (eo == 0) {   // lanes 0..3 write the 16-dim row
        float di = g_dinv[wid];
        float4 hv = *reinterpret_cast<const float4*>(&g_h1[(size_t)wid * HID + c * 4]);
        float4 bb = *reinterpret_cast<const float4*>(&b1[c * 4]);
        float4 r;
        r.x = fmaxf(di * (acc.x + hv.x) + bb.x, 0.f) * di;   // pre-scale for layer 2
        r.y = fmaxf(di * (acc.y + hv.y) + bb.y, 0.f) * di;
        r.z = fmaxf(di * (acc.z + hv.z) + bb.z, 0.f) * di;
        r.w = fmaxf(di * (acc.w + hv.w) + bb.w, 0.f) * di;
        *reinterpret_cast<float4*>(&g_hr[(size_t)wid * HID + c * 4]) = r;
    }
}

// ---------------- gather layer 2: float4 gather + fused W2 GEMM + log-softmax ----------------
__global__ void __launch_bounds__(256) k_gather2(const float* __restrict__ W2,
                                                 const float* __restrict__ b2,
                                                 float* __restrict__ out, int n) {
    __shared__ float W2s[HID * OUT_CH];  // 4 KB
    if (blockIdx.x == 0 && threadIdx.x == 0) g_c_scan = 0;   // reset for next replay
    for (int i = threadIdx.x; i < HID * OUT_CH; i += 256) W2s[i] = W2[i];
    __syncthreads();

    int wid = (blockIdx.x * 256 + threadIdx.x) >> 5;
    if (wid >= n) return;
    int lane = threadIdx.x & 31;
    int c  = lane & 3;
    int eo = lane >> 2;
    int row = g_rowptr[wid], end = g_rowptr[wid + 1];

    float4 acc = make_float4(0.f, 0.f, 0.f, 0.f);
    for (int i = row + eo; i < end; i += 8) {
        int s = g_csr[i];
        float4 hv = *reinterpret_cast<const float4*>(&g_hr[(size_t)s * HID + c * 4]);
        acc.x += hv.x; acc.y += hv.y; acc.z += hv.z; acc.w += hv.w;
    }
#pragma unroll
    for (int o = 4; o <= 16; o <<= 1) {
        acc.x += __shfl_xor_sync(0xffffffffu, acc.x, o);
        acc.y += __shfl_xor_sync(0xffffffffu, acc.y, o);
        acc.z += __shfl_xor_sync(0xffffffffu, acc.z, o);
        acc.w += __shfl_xor_sync(0xffffffffu, acc.w, o);
    }

    // every lane holds quad c: t[c*4 .. c*4+3]
    float di = g_dinv[wid];
    float4 hv = *reinterpret_cast<const float4*>(&g_hr[(size_t)wid * HID + c * 4]);
    float4 tq;
    tq.x = di * (acc.x + hv.x);
    tq.y = di * (acc.y + hv.y);
    tq.z = di * (acc.z + hv.z);
    tq.w = di * (acc.w + hv.w);

    float y0 = b2[lane];
    float y1 = b2[lane + 32];
#pragma unroll
    for (int q = 0; q < 4; q++) {   // broadcast quad q from lane q
        float a0 = __shfl_sync(0xffffffffu, tq.x, q);
        float a1 = __shfl_sync(0xffffffffu, tq.y, q);
        float a2 = __shfl_sync(0xffffffffu, tq.z, q);
        float a3 = __shfl_sync(0xffffffffu, tq.w, q);
        y0 += a0 * W2s[(4 * q + 0) * OUT_CH + lane]
            + a1 * W2s[(4 * q + 1) * OUT_CH + lane]
            + a2 * W2s[(4 * q + 2) * OUT_CH + lane]
            + a3 * W2s[(4 * q + 3) * OUT_CH + lane];
        y1 += a0 * W2s[(4 * q + 0) * OUT_CH + lane + 32]
            + a1 * W2s[(4 * q + 1) * OUT_CH + lane + 32]
            + a2 * W2s[(4 * q + 2) * OUT_CH + lane + 32]
            + a3 * W2s[(4 * q + 3) * OUT_CH + lane + 32];
    }
    float m = fmaxf(y0, y1);
#pragma unroll
    for (int o = 16; o; o >>= 1) m = fmaxf(m, __shfl_xor_sync(0xffffffffu, m, o));
    float se = expf(y0 - m) + expf(y1 - m);
#pragma unroll
    for (int o = 16; o; o >>= 1) se += __shfl_xor_sync(0xffffffffu, se, o);
    float lg = m + logf(se);
    out[(size_t)wid * OUT_CH + lane]      = y0 - lg;
    out[(size_t)wid * OUT_CH + lane + 32] = y1 - lg;
}

// ---------------- launch ----------------
extern "C" void kernel_launch(void* const* d_in, const int* in_sizes, int n_in,
                              void* d_out, int out_size) {
    const float* x    = (const float*)d_in[0];
    const int*   ei   = (const int*)d_in[1];     // int32 (JAX x64 disabled)
    const float* W1   = (const float*)d_in[2];
    const float* b1   = (const float*)d_in[3];
    const float* W2   = (const float*)d_in[4];
    const float* b2   = (const float*)d_in[5];
    float* out        = (float*)d_out;

    const int n = in_sizes[0] / IN_CH;       // 100000
    const int e = in_sizes[1] / 2;           // 3200000
    const int* src = ei;
    const int* dst = ei + e;

    const int TB = 256;
    int gb_e = (e + TB - 1) / TB;            // 12500
    int gb_w = (n * 32 + TB - 1) / TB;       // warp-per-node kernels

    k_hist<<<gb_e, TB>>>(dst, e);                          // 1
    k_ck<<<2 * NBLK + gb_e, TB>>>(x, W1, src, dst, n, e);  // 2 (gemm+scan+scatter)
    k_gather1<<<gb_w, TB>>>(b1, n);                        // 3
    k_gather2<<<gb_w, TB>>>(W2, b2, out, n);               // 4 <-- profiled
}